// round 2
// baseline (speedup 1.0000x reference)
#include <cuda_runtime.h>
#include <math.h>

#define K_CODES 2048
#define DDIM    512
#define BDIM    64
#define TDIM    256
#define N_ROWS  (BDIM*TDIM)        /* 16384 */
#define QN      (BDIM*DDIM*TDIM)   /* 8388608 */
#define OUT_LOSS 0
#define OUT_Q    1
#define OUT_PERP (1+QN)
#define OUT_IDX  (2+QN)

/* dynamic smem layout (floats):
   A_s   [512][64]      0      .. 32768
   Wt_s  [64][68]       32768  .. 37120   (k-major, pad 68)
   dist_s[64][65]       37120  .. 41280
   fsq_s [64]           41280  .. 41344
   wsq_s [64]           41344  .. 41408
   red_s [8]            41408  .. 41416
*/
#define SMEM_FLOATS 41416

__device__ float g_wsq[K_CODES];
__device__ int   g_counts[K_CODES];
__device__ float g_partials[256];

__global__ void init_kernel() {
    int i = blockIdx.x * blockDim.x + threadIdx.x;
    if (i < K_CODES) g_counts[i] = 0;
}

__global__ void wsq_kernel(const float* __restrict__ W) {
    int warp = (blockIdx.x * blockDim.x + threadIdx.x) >> 5;
    int lane = threadIdx.x & 31;
    if (warp >= K_CODES) return;
    const float* row = W + (size_t)warp * DDIM;
    float s = 0.f;
    #pragma unroll
    for (int d = lane; d < DDIM; d += 32) { float v = row[d]; s += v * v; }
    #pragma unroll
    for (int o = 16; o > 0; o >>= 1) s += __shfl_xor_sync(0xffffffffu, s, o);
    if (lane == 0) g_wsq[warp] = s;
}

__global__ __launch_bounds__(256, 1)
void vq_main(const float* __restrict__ x, const float* __restrict__ W,
             float* __restrict__ out) {
    extern __shared__ float sm[];
    float* A_s    = sm;                 // [512][64]  k-major
    float* Wt_s   = sm + 32768;         // [64][68]   k-major
    float* dist_s = sm + 37120;         // [64][65]
    float* fsq_s  = sm + 41280;         // [64]
    float* wsq_s  = sm + 41344;         // [64]
    float* red_s  = sm + 41408;         // [8]

    const int tid = threadIdx.x;
    const int tx  = tid & 15;
    const int ty  = tid >> 4;
    const int gr0 = blockIdx.x * 64;    // first global row of this block
    const int b   = gr0 >> 8;           // batch index (64 rows stay in one b)
    const int t0  = gr0 & 255;          // time offset

    const float* xb = x + (size_t)b * (DDIM * TDIM) + t0;

    // ---- load A tile: A_s[d][r] = x[b][d][t0+r] (coalesced over r) ----
    for (int i = tid; i < DDIM * 64; i += 256) {
        int d = i >> 6, r = i & 63;
        A_s[d * 64 + r] = xb[(size_t)d * TDIM + r];
    }
    __syncthreads();

    // ---- fsq per row ----
    if (tid < 64) {
        float s = 0.f;
        for (int d = 0; d < DDIM; d++) { float v = A_s[d * 64 + tid]; s += v * v; }
        fsq_s[tid] = s;
    }

    // running top-3 (row-owner threads tid<64, row = tid)
    float bd0 = INFINITY, bd1 = INFINITY, bd2 = INFINITY;
    int   bi0 = 0, bi1 = 0, bi2 = 0;

    const int lc = tid & 63;            // code this thread loads
    const int lk = (tid >> 6) * 16;     // k-offset this thread loads

    for (int p = 0; p < 32; p++) {
        const int c0 = p * 64;
        if (tid < 64) wsq_s[tid] = g_wsq[c0 + tid];

        float acc[4][4];
        #pragma unroll
        for (int i = 0; i < 4; i++)
            #pragma unroll
            for (int j = 0; j < 4; j++) acc[i][j] = 0.f;

        for (int kk = 0; kk < 8; kk++) {
            const int k0 = kk * 64;
            __syncthreads();   // Wt_s free (also: owners finished prior scan, wsq ready)
            // load W chunk: 64 codes x 64 k, store k-major, conflict-free STS
            {
                const float4* wsrc =
                    (const float4*)(W + (size_t)(c0 + lc) * DDIM + k0 + lk);
                #pragma unroll
                for (int j = 0; j < 4; j++) {
                    float4 v = wsrc[j];
                    int kb = lk + j * 4;
                    Wt_s[(kb + 0) * 68 + lc] = v.x;
                    Wt_s[(kb + 1) * 68 + lc] = v.y;
                    Wt_s[(kb + 2) * 68 + lc] = v.z;
                    Wt_s[(kb + 3) * 68 + lc] = v.w;
                }
            }
            __syncthreads();
            #pragma unroll 16
            for (int k = 0; k < 64; k++) {
                float4 a  = *(const float4*)(A_s + (size_t)(k0 + k) * 64 + ty * 4);
                float4 bb = *(const float4*)(Wt_s + k * 68 + tx * 4);
                acc[0][0] += a.x * bb.x; acc[0][1] += a.x * bb.y;
                acc[0][2] += a.x * bb.z; acc[0][3] += a.x * bb.w;
                acc[1][0] += a.y * bb.x; acc[1][1] += a.y * bb.y;
                acc[1][2] += a.y * bb.z; acc[1][3] += a.y * bb.w;
                acc[2][0] += a.z * bb.x; acc[2][1] += a.z * bb.y;
                acc[2][2] += a.z * bb.z; acc[2][3] += a.z * bb.w;
                acc[3][0] += a.w * bb.x; acc[3][1] += a.w * bb.y;
                acc[3][2] += a.w * bb.z; acc[3][3] += a.w * bb.w;
            }
        }

        // write dists, replicating reference rounding: (fsq + wsq) - (2*dot)
        #pragma unroll
        for (int i = 0; i < 4; i++) {
            int ry = ty * 4 + i;
            float fs = fsq_s[ry];
            #pragma unroll
            for (int j = 0; j < 4; j++) {
                int cx = tx * 4 + j;
                float t1 = __fadd_rn(fs, wsq_s[cx]);
                float dd = __fadd_rn(t1, -__fmul_rn(2.0f, acc[i][j]));
                dist_s[ry * 65 + cx] = dd;
            }
        }
        __syncthreads();

        if (tid < 64) {
            #pragma unroll 8
            for (int c = 0; c < 64; c++) {
                float dv = dist_s[tid * 65 + c];
                int code = c0 + c;
                if (dv < bd0) {
                    bd2 = bd1; bi2 = bi1; bd1 = bd0; bi1 = bi0; bd0 = dv; bi0 = code;
                } else if (dv < bd1) {
                    bd2 = bd1; bi2 = bi1; bd1 = dv; bi1 = code;
                } else if (dv < bd2) {
                    bd2 = dv; bi2 = code;
                }
            }
        }
        // next panel's first __syncthreads separates scan from dist_s overwrite
    }
    __syncthreads();

    int* idx_s = (int*)dist_s;   // safe reuse after barrier
    if (tid < 64) {
        idx_s[tid * 3 + 0] = bi0;
        idx_s[tid * 3 + 1] = bi1;
        idx_s[tid * 3 + 2] = bi2;
        atomicAdd(&g_counts[bi0], 1);
        atomicAdd(&g_counts[bi1], 1);
        atomicAdd(&g_counts[bi2], 1);
        out[OUT_IDX + gr0 + tid] = (float)bi2;   // encoding_indices = 3rd nearest
    }
    __syncthreads();

    // ---- quantized output + MSE partial ----
    float mse = 0.f;
    for (int it = 0; it < 128; it++) {
        int lin = it * 256 + tid;
        int r = lin & 63, d = lin >> 6;
        int j0 = idx_s[r * 3 + 0];
        int j1 = idx_s[r * 3 + 1];
        int j2 = idx_s[r * 3 + 2];
        float q = (W[(size_t)j0 * DDIM + d] +
                   W[(size_t)j1 * DDIM + d] +
                   W[(size_t)j2 * DDIM + d]) * (1.0f / 3.0f);
        out[OUT_Q + (size_t)(b * DDIM + d) * TDIM + t0 + r] = q;
        float df = q - A_s[d * 64 + r];
        mse += df * df;
    }
    #pragma unroll
    for (int o = 16; o > 0; o >>= 1) mse += __shfl_xor_sync(0xffffffffu, mse, o);
    if ((tid & 31) == 0) red_s[tid >> 5] = mse;
    __syncthreads();
    if (tid == 0) {
        float s = 0.f;
        #pragma unroll
        for (int i = 0; i < 8; i++) s += red_s[i];
        g_partials[blockIdx.x] = s;   // deterministic: fixed slot per block
    }
}

__global__ void finalize_kernel(float* __restrict__ out) {
    __shared__ float red[256];
    int tid = threadIdx.x;
    // loss = 1.25 * mean((q - x)^2)   (e_latent == q_latent numerically)
    red[tid] = g_partials[tid];
    __syncthreads();
    for (int s = 128; s > 0; s >>= 1) {
        if (tid < s) red[tid] += red[tid + s];
        __syncthreads();
    }
    if (tid == 0) out[OUT_LOSS] = 1.25f * (red[0] / (float)QN);
    __syncthreads();
    // perplexity
    float e = 0.f;
    for (int k = tid; k < K_CODES; k += 256) {
        float pr = (float)g_counts[k] * (1.0f / (float)N_ROWS);
        e += pr * logf(pr + 1e-10f);
    }
    red[tid] = e;
    __syncthreads();
    for (int s = 128; s > 0; s >>= 1) {
        if (tid < s) red[tid] += red[tid + s];
        __syncthreads();
    }
    if (tid == 0) out[OUT_PERP] = expf(-red[0]);
}

extern "C" void kernel_launch(void* const* d_in, const int* in_sizes, int n_in,
                              void* d_out, int out_size) {
    const float* x = (const float*)d_in[0];
    const float* W = (const float*)d_in[1];
    float* out = (float*)d_out;
    (void)in_sizes; (void)n_in; (void)out_size;

    cudaFuncSetAttribute(vq_main, cudaFuncAttributeMaxDynamicSharedMemorySize,
                         SMEM_FLOATS * 4);

    init_kernel<<<8, 256>>>();
    wsq_kernel<<<256, 256>>>(W);
    vq_main<<<256, 256, SMEM_FLOATS * 4>>>(x, W, out);
    finalize_kernel<<<1, 256>>>(out);
}

// round 6
// speedup vs baseline: 1.7307x; 1.7307x over previous
#include <cuda_runtime.h>
#include <math.h>
#include <stdint.h>

#define K_CODES 2048
#define DDIM    512
#define N_ROWS  16384
#define QN      8388608
#define OUT_LOSS 0
#define OUT_Q    1
#define OUT_PERP (1+QN)
#define OUT_IDX  (2+QN)

#define BM 128
#define BN 128
#define BK 32
#define NPANEL (K_CODES/BN)   /* 16 */
#define NCHUNK (DDIM/BK)      /* 16 */

/* smem float offsets */
#define SA0   0
#define SA1   4096
#define SB0   8192
#define SB1   12288
#define SDIST 16384            /* 128 x 129 */
#define SFSQ  32896
#define SWSQ  33024
#define SRED  33152
#define SIDX  33160            /* 384 ints */
#define SMEM_FLOATS 33544
#define SMEM_BYTES  (SMEM_FLOATS*4)
#define SQS   0                /* q-staging reuses A/B region: 32x128 */

__device__ float g_wt[(size_t)DDIM * K_CODES];   /* Wt[d][c] */
__device__ float g_wsq[K_CODES];
__device__ float g_fsq[N_ROWS];
__device__ int   g_counts[K_CODES];
__device__ float g_partials[128];

__device__ __forceinline__ unsigned long long pack2(float v) {
    unsigned long long r;
    asm("mov.b64 %0, {%1,%1};" : "=l"(r) : "f"(v));
    return r;
}
__device__ __forceinline__ unsigned long long fma2(unsigned long long a,
                                                   unsigned long long b,
                                                   unsigned long long c) {
    unsigned long long d;
    asm("fma.rn.f32x2 %0, %1, %2, %3;" : "=l"(d) : "l"(a), "l"(b), "l"(c));
    return d;
}
__device__ __forceinline__ void unpack2(unsigned long long v, float& lo, float& hi) {
    asm("mov.b64 {%0,%1}, %2;" : "=f"(lo), "=f"(hi) : "l"(v));
}

/* ---------------- prep ---------------- */
__global__ void init_counts() {
    int i = blockIdx.x * blockDim.x + threadIdx.x;
    if (i < K_CODES) g_counts[i] = 0;
}

__global__ void wsq_kernel(const float* __restrict__ W) {
    int warp = (blockIdx.x * blockDim.x + threadIdx.x) >> 5;
    int lane = threadIdx.x & 31;
    if (warp >= K_CODES) return;
    const float* row = W + (size_t)warp * DDIM;
    float s = 0.f;
    #pragma unroll
    for (int d = lane; d < DDIM; d += 32) { float v = row[d]; s += v * v; }
    #pragma unroll
    for (int o = 16; o > 0; o >>= 1) s += __shfl_xor_sync(0xffffffffu, s, o);
    if (lane == 0) g_wsq[warp] = s;
}

__global__ void fsq_kernel(const float* __restrict__ x) {
    int b = blockIdx.x, t = threadIdx.x;
    const float* p = x + (size_t)b * DDIM * 256 + t;
    float s = 0.f;
    for (int d = 0; d < DDIM; d++) { float v = p[(size_t)d * 256]; s += v * v; }
    g_fsq[b * 256 + t] = s;
}

__global__ void wt_kernel(const float* __restrict__ W) {
    __shared__ float sh[32][33];
    int c0 = blockIdx.x * 32, d0 = blockIdx.y * 32;
    int tx = threadIdx.x & 31, ty = threadIdx.x >> 5;   /* 32 x 8 */
    #pragma unroll
    for (int i = 0; i < 4; i++)
        sh[ty + 8 * i][tx] = W[(size_t)(c0 + ty + 8 * i) * DDIM + d0 + tx];
    __syncthreads();
    #pragma unroll
    for (int i = 0; i < 4; i++)
        g_wt[(size_t)(d0 + ty + 8 * i) * K_CODES + c0 + tx] = sh[tx][ty + 8 * i];
}

/* ---------------- main ---------------- */
__global__ __launch_bounds__(256, 1)
void vq_main(const float* __restrict__ x, const float* __restrict__ W,
             float* __restrict__ out) {
    extern __shared__ float sm[];
    float* dist_s = sm + SDIST;
    float* fsq_s  = sm + SFSQ;
    float* wsq_s  = sm + SWSQ;
    float* red_s  = sm + SRED;
    int*   idx_s  = (int*)(sm + SIDX);

    const int tid = threadIdx.x;
    const int wid = tid >> 5;
    const int lane = tid & 31;
    const int tx = tid & 15;       /* code group */
    const int ty = tid >> 4;       /* row group */
    const int gr0 = blockIdx.x * BM;
    const int b   = gr0 >> 8;
    const int t0  = gr0 & 255;

    const float* xb = x + (size_t)b * (DDIM * 256) + t0;

    if (tid < BM) fsq_s[tid] = g_fsq[gr0 + tid];

    /* tile load indices: 256 threads, per pass 8 k-rows x 32 float4 */
    const int lk = tid >> 5;       /* 0..7 */
    const int lr4 = (tid & 31) * 4;

    float bd0 = INFINITY, bd1 = INFINITY, bd2 = INFINITY;
    int   bi0 = 0, bi1 = 0, bi2 = 0;

    for (int p = 0; p < NPANEL; p++) {
        const int c0 = p * BN;
        __syncthreads();                       /* dist/wsq reuse safe */
        if (tid < BN) wsq_s[tid] = g_wsq[c0 + tid];

        unsigned long long acc[32];
        #pragma unroll
        for (int i = 0; i < 32; i++) acc[i] = 0ULL;

        float4 pa[4], pb[4];
        /* preload chunk 0 */
        #pragma unroll
        for (int i = 0; i < 4; i++) {
            int k = i * 8 + lk;
            pa[i] = *(const float4*)(xb + (size_t)k * 256 + lr4);
            pb[i] = *(const float4*)(g_wt + (size_t)k * K_CODES + c0 + lr4);
        }
        #pragma unroll
        for (int i = 0; i < 4; i++) {
            int k = i * 8 + lk;
            *(float4*)(sm + SA0 + k * 128 + lr4) = pa[i];
            *(float4*)(sm + SB0 + k * 128 + lr4) = pb[i];
        }
        __syncthreads();

        for (int kk = 0; kk < NCHUNK; kk++) {
            const float* A = sm + (kk & 1 ? SA1 : SA0);
            const float* B = sm + (kk & 1 ? SB1 : SB0);
            if (kk < NCHUNK - 1) {
                const int kf = (kk + 1) * BK;
                #pragma unroll
                for (int i = 0; i < 4; i++) {
                    int k = kf + i * 8 + lk;
                    pa[i] = *(const float4*)(xb + (size_t)k * 256 + lr4);
                    pb[i] = *(const float4*)(g_wt + (size_t)k * K_CODES + c0 + lr4);
                }
            }
            #pragma unroll 8
            for (int k = 0; k < BK; k++) {
                unsigned long long aP[4];
                #pragma unroll
                for (int ii = 0; ii < 4; ii++)
                    aP[ii] = *(const unsigned long long*)(A + k * 128 + ty * 8 + ii * 2);
                unsigned long long bD[8];
                #pragma unroll
                for (int j = 0; j < 8; j++)
                    bD[j] = pack2(B[k * 128 + tx + 16 * j]);
                #pragma unroll
                for (int ii = 0; ii < 4; ii++)
                    #pragma unroll
                    for (int j = 0; j < 8; j++)
                        acc[ii * 8 + j] = fma2(aP[ii], bD[j], acc[ii * 8 + j]);
            }
            __syncthreads();
            if (kk < NCHUNK - 1) {
                const int dst = ((kk + 1) & 1) ? SA1 : SA0;
                const int dstb = ((kk + 1) & 1) ? SB1 : SB0;
                #pragma unroll
                for (int i = 0; i < 4; i++) {
                    int k = i * 8 + lk;
                    *(float4*)(sm + dst + k * 128 + lr4) = pa[i];
                    *(float4*)(sm + dstb + k * 128 + lr4) = pb[i];
                }
                __syncthreads();
            }
        }

        /* distances, exact reference rounding */
        #pragma unroll
        for (int ii = 0; ii < 4; ii++) {
            const int r0 = ty * 8 + ii * 2;
            const float f0 = fsq_s[r0], f1 = fsq_s[r0 + 1];
            #pragma unroll
            for (int j = 0; j < 8; j++) {
                const int c = tx + 16 * j;
                float lo, hi;
                unpack2(acc[ii * 8 + j], lo, hi);
                float ws = wsq_s[c];
                dist_s[r0 * 129 + c] =
                    __fadd_rn(__fadd_rn(f0, ws), -__fmul_rn(2.0f, lo));
                dist_s[(r0 + 1) * 129 + c] =
                    __fadd_rn(__fadd_rn(f1, ws), -__fmul_rn(2.0f, hi));
            }
        }
        __syncthreads();

        if (tid < BM) {
            #pragma unroll 4
            for (int c = 0; c < BN; c++) {
                float dv = dist_s[tid * 129 + c];
                int code = c0 + c;
                if (dv < bd0) {
                    bd2 = bd1; bi2 = bi1; bd1 = bd0; bi1 = bi0; bd0 = dv; bi0 = code;
                } else if (dv < bd1) {
                    bd2 = bd1; bi2 = bi1; bd1 = dv; bi1 = code;
                } else if (dv < bd2) {
                    bd2 = dv; bi2 = code;
                }
            }
        }
    }
    __syncthreads();

    if (tid < BM) {
        idx_s[tid * 3 + 0] = bi0;
        idx_s[tid * 3 + 1] = bi1;
        idx_s[tid * 3 + 2] = bi2;
        atomicAdd(&g_counts[bi0], 1);
        atomicAdd(&g_counts[bi1], 1);
        atomicAdd(&g_counts[bi2], 1);
        out[OUT_IDX + gr0 + tid] = (float)bi2;
    }
    __syncthreads();

    /* quantized output + MSE, staged through smem */
    float* q_s = sm + SQS;          /* [32][128] */
    float mse = 0.f;
    const int r  = tid & 127;
    const int dh = tid >> 7;
    const int j0 = idx_s[r * 3 + 0];
    const int j1 = idx_s[r * 3 + 1];
    const int j2 = idx_s[r * 3 + 2];
    for (int dc = 0; dc < 16; dc++) {
        const int d0 = dc * 32 + dh * 16;
        #pragma unroll
        for (int q4 = 0; q4 < 4; q4++) {
            float4 a = *(const float4*)(W + (size_t)j0 * DDIM + d0 + q4 * 4);
            float4 bb = *(const float4*)(W + (size_t)j1 * DDIM + d0 + q4 * 4);
            float4 cc = *(const float4*)(W + (size_t)j2 * DDIM + d0 + q4 * 4);
            int dl = dh * 16 + q4 * 4;
            q_s[(dl + 0) * 128 + r] = (a.x + bb.x + cc.x) * (1.0f / 3.0f);
            q_s[(dl + 1) * 128 + r] = (a.y + bb.y + cc.y) * (1.0f / 3.0f);
            q_s[(dl + 2) * 128 + r] = (a.z + bb.z + cc.z) * (1.0f / 3.0f);
            q_s[(dl + 3) * 128 + r] = (a.w + bb.w + cc.w) * (1.0f / 3.0f);
        }
        __syncthreads();
        #pragma unroll
        for (int i = 0; i < 16; i++) {
            int lin = i * 256 + tid, dl = lin >> 7, rr = lin & 127;
            int d = dc * 32 + dl;
            size_t go = (size_t)(b * DDIM + d) * 256 + t0 + rr;
            float qv = q_s[dl * 128 + rr];
            out[OUT_Q + go] = qv;
            float df = qv - x[go];
            mse += df * df;
        }
        __syncthreads();
    }
    #pragma unroll
    for (int o = 16; o > 0; o >>= 1) mse += __shfl_xor_sync(0xffffffffu, mse, o);
    if (lane == 0) red_s[wid] = mse;
    __syncthreads();
    if (tid == 0) {
        float s = 0.f;
        #pragma unroll
        for (int i = 0; i < 8; i++) s += red_s[i];
        g_partials[blockIdx.x] = s;
    }
}

__global__ void finalize_kernel(float* __restrict__ out) {
    __shared__ float red[256];
    int tid = threadIdx.x;
    red[tid] = (tid < 128) ? g_partials[tid] : 0.f;
    __syncthreads();
    for (int s = 128; s > 0; s >>= 1) {
        if (tid < s) red[tid] += red[tid + s];
        __syncthreads();
    }
    if (tid == 0) out[OUT_LOSS] = 1.25f * (red[0] / (float)QN);
    __syncthreads();
    float e = 0.f;
    for (int k = tid; k < K_CODES; k += 256) {
        float pr = (float)g_counts[k] * (1.0f / (float)N_ROWS);
        e += pr * logf(pr + 1e-10f);
    }
    red[tid] = e;
    __syncthreads();
    for (int s = 128; s > 0; s >>= 1) {
        if (tid < s) red[tid] += red[tid + s];
        __syncthreads();
    }
    if (tid == 0) out[OUT_PERP] = expf(-red[0]);
}

extern "C" void kernel_launch(void* const* d_in, const int* in_sizes, int n_in,
                              void* d_out, int out_size) {
    const float* x = (const float*)d_in[0];
    const float* W = (const float*)d_in[1];
    float* out = (float*)d_out;
    (void)in_sizes; (void)n_in; (void)out_size;

    cudaFuncSetAttribute(vq_main, cudaFuncAttributeMaxDynamicSharedMemorySize,
                         SMEM_BYTES);

    init_counts<<<8, 256>>>();
    wsq_kernel<<<256, 256>>>(W);
    fsq_kernel<<<64, 256>>>(x);
    wt_kernel<<<dim3(64, 16), 256>>>(W);
    vq_main<<<128, 256, SMEM_BYTES>>>(x, W, out);
    finalize_kernel<<<1, 256>>>(out);
}

// round 7
// speedup vs baseline: 1.7363x; 1.0033x over previous
#include <cuda_runtime.h>
#include <math.h>
#include <stdint.h>

#define K_CODES 2048
#define DDIM    512
#define N_ROWS  16384
#define QN      8388608
#define OUT_LOSS 0
#define OUT_Q    1
#define OUT_PERP (1+QN)
#define OUT_IDX  (2+QN)

#define BM 128
#define BN 128
#define BK 32
#define NPANEL (K_CODES/BN)   /* 16 */
#define NCHUNK (DDIM/BK)      /* 16 */

/* smem float offsets */
#define SA0   0
#define SA1   4096
#define SB0   8192
#define SB1   12288
#define SDIST 16384            /* 128 x 129 */
#define SFSQ  32896
#define SWSQ  33024
#define SRED  33152
#define SIDX  33160            /* 384 ints */
#define SMEM_FLOATS 33544
#define SMEM_BYTES  (SMEM_FLOATS*4)
#define SQS   0                /* q-staging reuses A/B region: 32x128 */

__device__ float g_wt[(size_t)DDIM * K_CODES];   /* Wt[d][c] */
__device__ float g_wsq[K_CODES];
__device__ float g_fsq[N_ROWS];
__device__ int   g_counts[K_CODES];
__device__ float g_partials[128];

__device__ __forceinline__ unsigned long long pack2(float v) {
    unsigned long long r;
    asm("mov.b64 %0, {%1,%1};" : "=l"(r) : "f"(v));
    return r;
}
__device__ __forceinline__ unsigned long long fma2(unsigned long long a,
                                                   unsigned long long b,
                                                   unsigned long long c) {
    unsigned long long d;
    asm("fma.rn.f32x2 %0, %1, %2, %3;" : "=l"(d) : "l"(a), "l"(b), "l"(c));
    return d;
}
__device__ __forceinline__ void unpack2(unsigned long long v, float& lo, float& hi) {
    asm("mov.b64 {%0,%1}, %2;" : "=f"(lo), "=f"(hi) : "l"(v));
}

/* ---------------- prep ---------------- */
__global__ void init_counts() {
    int i = blockIdx.x * blockDim.x + threadIdx.x;
    if (i < K_CODES) g_counts[i] = 0;
}

__global__ void wsq_kernel(const float* __restrict__ W) {
    int warp = (blockIdx.x * blockDim.x + threadIdx.x) >> 5;
    int lane = threadIdx.x & 31;
    if (warp >= K_CODES) return;
    const float* row = W + (size_t)warp * DDIM;
    float s = 0.f;
    #pragma unroll
    for (int d = lane; d < DDIM; d += 32) { float v = row[d]; s += v * v; }
    #pragma unroll
    for (int o = 16; o > 0; o >>= 1) s += __shfl_xor_sync(0xffffffffu, s, o);
    if (lane == 0) g_wsq[warp] = s;
}

__global__ void fsq_kernel(const float* __restrict__ x) {
    int b = blockIdx.x, t = threadIdx.x;
    const float* p = x + (size_t)b * DDIM * 256 + t;
    float s = 0.f;
    for (int d = 0; d < DDIM; d++) { float v = p[(size_t)d * 256]; s += v * v; }
    g_fsq[b * 256 + t] = s;
}

__global__ void wt_kernel(const float* __restrict__ W) {
    __shared__ float sh[32][33];
    int c0 = blockIdx.x * 32, d0 = blockIdx.y * 32;
    int tx = threadIdx.x & 31, ty = threadIdx.x >> 5;   /* 32 x 8 */
    #pragma unroll
    for (int i = 0; i < 4; i++)
        sh[ty + 8 * i][tx] = W[(size_t)(c0 + ty + 8 * i) * DDIM + d0 + tx];
    __syncthreads();
    #pragma unroll
    for (int i = 0; i < 4; i++)
        g_wt[(size_t)(d0 + ty + 8 * i) * K_CODES + c0 + tx] = sh[tx][ty + 8 * i];
}

/* ---------------- main ---------------- */
__global__ __launch_bounds__(256, 1)
void vq_main(const float* __restrict__ x, const float* __restrict__ W,
             float* __restrict__ out) {
    extern __shared__ float sm[];
    float* dist_s = sm + SDIST;
    float* fsq_s  = sm + SFSQ;
    float* wsq_s  = sm + SWSQ;
    float* red_s  = sm + SRED;
    int*   idx_s  = (int*)(sm + SIDX);

    const int tid = threadIdx.x;
    const int wid = tid >> 5;
    const int lane = tid & 31;
    const int tx = tid & 15;       /* code group */
    const int ty = tid >> 4;       /* row group */
    const int gr0 = blockIdx.x * BM;
    const int b   = gr0 >> 8;
    const int t0  = gr0 & 255;

    const float* xb = x + (size_t)b * (DDIM * 256) + t0;

    if (tid < BM) fsq_s[tid] = g_fsq[gr0 + tid];

    /* tile load indices: 256 threads, per pass 8 k-rows x 32 float4 */
    const int lk = tid >> 5;       /* 0..7 */
    const int lr4 = (tid & 31) * 4;

    float bd0 = INFINITY, bd1 = INFINITY, bd2 = INFINITY;
    int   bi0 = 0, bi1 = 0, bi2 = 0;

    for (int p = 0; p < NPANEL; p++) {
        const int c0 = p * BN;
        __syncthreads();                       /* dist/wsq reuse safe */
        if (tid < BN) wsq_s[tid] = g_wsq[c0 + tid];

        unsigned long long acc[32];
        #pragma unroll
        for (int i = 0; i < 32; i++) acc[i] = 0ULL;

        float4 pa[4], pb[4];
        /* preload chunk 0 */
        #pragma unroll
        for (int i = 0; i < 4; i++) {
            int k = i * 8 + lk;
            pa[i] = *(const float4*)(xb + (size_t)k * 256 + lr4);
            pb[i] = *(const float4*)(g_wt + (size_t)k * K_CODES + c0 + lr4);
        }
        #pragma unroll
        for (int i = 0; i < 4; i++) {
            int k = i * 8 + lk;
            *(float4*)(sm + SA0 + k * 128 + lr4) = pa[i];
            *(float4*)(sm + SB0 + k * 128 + lr4) = pb[i];
        }
        __syncthreads();

        for (int kk = 0; kk < NCHUNK; kk++) {
            const float* A = sm + (kk & 1 ? SA1 : SA0);
            const float* B = sm + (kk & 1 ? SB1 : SB0);
            if (kk < NCHUNK - 1) {
                const int kf = (kk + 1) * BK;
                #pragma unroll
                for (int i = 0; i < 4; i++) {
                    int k = kf + i * 8 + lk;
                    pa[i] = *(const float4*)(xb + (size_t)k * 256 + lr4);
                    pb[i] = *(const float4*)(g_wt + (size_t)k * K_CODES + c0 + lr4);
                }
            }
            #pragma unroll 8
            for (int k = 0; k < BK; k++) {
                unsigned long long aP[4];
                #pragma unroll
                for (int ii = 0; ii < 4; ii++)
                    aP[ii] = *(const unsigned long long*)(A + k * 128 + ty * 8 + ii * 2);
                unsigned long long bD[8];
                #pragma unroll
                for (int j = 0; j < 8; j++)
                    bD[j] = pack2(B[k * 128 + tx + 16 * j]);
                #pragma unroll
                for (int ii = 0; ii < 4; ii++)
                    #pragma unroll
                    for (int j = 0; j < 8; j++)
                        acc[ii * 8 + j] = fma2(aP[ii], bD[j], acc[ii * 8 + j]);
            }
            __syncthreads();
            if (kk < NCHUNK - 1) {
                const int dst = ((kk + 1) & 1) ? SA1 : SA0;
                const int dstb = ((kk + 1) & 1) ? SB1 : SB0;
                #pragma unroll
                for (int i = 0; i < 4; i++) {
                    int k = i * 8 + lk;
                    *(float4*)(sm + dst + k * 128 + lr4) = pa[i];
                    *(float4*)(sm + dstb + k * 128 + lr4) = pb[i];
                }
                __syncthreads();
            }
        }

        /* distances, exact reference rounding */
        #pragma unroll
        for (int ii = 0; ii < 4; ii++) {
            const int r0 = ty * 8 + ii * 2;
            const float f0 = fsq_s[r0], f1 = fsq_s[r0 + 1];
            #pragma unroll
            for (int j = 0; j < 8; j++) {
                const int c = tx + 16 * j;
                float lo, hi;
                unpack2(acc[ii * 8 + j], lo, hi);
                float ws = wsq_s[c];
                dist_s[r0 * 129 + c] =
                    __fadd_rn(__fadd_rn(f0, ws), -__fmul_rn(2.0f, lo));
                dist_s[(r0 + 1) * 129 + c] =
                    __fadd_rn(__fadd_rn(f1, ws), -__fmul_rn(2.0f, hi));
            }
        }
        __syncthreads();

        if (tid < BM) {
            #pragma unroll 4
            for (int c = 0; c < BN; c++) {
                float dv = dist_s[tid * 129 + c];
                int code = c0 + c;
                if (dv < bd0) {
                    bd2 = bd1; bi2 = bi1; bd1 = bd0; bi1 = bi0; bd0 = dv; bi0 = code;
                } else if (dv < bd1) {
                    bd2 = bd1; bi2 = bi1; bd1 = dv; bi1 = code;
                } else if (dv < bd2) {
                    bd2 = dv; bi2 = code;
                }
            }
        }
    }
    __syncthreads();

    if (tid < BM) {
        idx_s[tid * 3 + 0] = bi0;
        idx_s[tid * 3 + 1] = bi1;
        idx_s[tid * 3 + 2] = bi2;
        atomicAdd(&g_counts[bi0], 1);
        atomicAdd(&g_counts[bi1], 1);
        atomicAdd(&g_counts[bi2], 1);
        out[OUT_IDX + gr0 + tid] = (float)bi2;
    }
    __syncthreads();

    /* quantized output + MSE, staged through smem */
    float* q_s = sm + SQS;          /* [32][128] */
    float mse = 0.f;
    const int r  = tid & 127;
    const int dh = tid >> 7;
    const int j0 = idx_s[r * 3 + 0];
    const int j1 = idx_s[r * 3 + 1];
    const int j2 = idx_s[r * 3 + 2];
    for (int dc = 0; dc < 16; dc++) {
        const int d0 = dc * 32 + dh * 16;
        #pragma unroll
        for (int q4 = 0; q4 < 4; q4++) {
            float4 a = *(const float4*)(W + (size_t)j0 * DDIM + d0 + q4 * 4);
            float4 bb = *(const float4*)(W + (size_t)j1 * DDIM + d0 + q4 * 4);
            float4 cc = *(const float4*)(W + (size_t)j2 * DDIM + d0 + q4 * 4);
            int dl = dh * 16 + q4 * 4;
            q_s[(dl + 0) * 128 + r] = (a.x + bb.x + cc.x) * (1.0f / 3.0f);
            q_s[(dl + 1) * 128 + r] = (a.y + bb.y + cc.y) * (1.0f / 3.0f);
            q_s[(dl + 2) * 128 + r] = (a.z + bb.z + cc.z) * (1.0f / 3.0f);
            q_s[(dl + 3) * 128 + r] = (a.w + bb.w + cc.w) * (1.0f / 3.0f);
        }
        __syncthreads();
        #pragma unroll
        for (int i = 0; i < 16; i++) {
            int lin = i * 256 + tid, dl = lin >> 7, rr = lin & 127;
            int d = dc * 32 + dl;
            size_t go = (size_t)(b * DDIM + d) * 256 + t0 + rr;
            float qv = q_s[dl * 128 + rr];
            out[OUT_Q + go] = qv;
            float df = qv - x[go];
            mse += df * df;
        }
        __syncthreads();
    }
    #pragma unroll
    for (int o = 16; o > 0; o >>= 1) mse += __shfl_xor_sync(0xffffffffu, mse, o);
    if (lane == 0) red_s[wid] = mse;
    __syncthreads();
    if (tid == 0) {
        float s = 0.f;
        #pragma unroll
        for (int i = 0; i < 8; i++) s += red_s[i];
        g_partials[blockIdx.x] = s;
    }
}

__global__ void finalize_kernel(float* __restrict__ out) {
    __shared__ float red[256];
    int tid = threadIdx.x;
    red[tid] = (tid < 128) ? g_partials[tid] : 0.f;
    __syncthreads();
    for (int s = 128; s > 0; s >>= 1) {
        if (tid < s) red[tid] += red[tid + s];
        __syncthreads();
    }
    if (tid == 0) out[OUT_LOSS] = 1.25f * (red[0] / (float)QN);
    __syncthreads();
    float e = 0.f;
    for (int k = tid; k < K_CODES; k += 256) {
        float pr = (float)g_counts[k] * (1.0f / (float)N_ROWS);
        e += pr * logf(pr + 1e-10f);
    }
    red[tid] = e;
    __syncthreads();
    for (int s = 128; s > 0; s >>= 1) {
        if (tid < s) red[tid] += red[tid + s];
        __syncthreads();
    }
    if (tid == 0) out[OUT_PERP] = expf(-red[0]);
}

extern "C" void kernel_launch(void* const* d_in, const int* in_sizes, int n_in,
                              void* d_out, int out_size) {
    const float* x = (const float*)d_in[0];
    const float* W = (const float*)d_in[1];
    float* out = (float*)d_out;
    (void)in_sizes; (void)n_in; (void)out_size;

    cudaFuncSetAttribute(vq_main, cudaFuncAttributeMaxDynamicSharedMemorySize,
                         SMEM_BYTES);

    init_counts<<<8, 256>>>();
    wsq_kernel<<<256, 256>>>(W);
    fsq_kernel<<<64, 256>>>(x);
    wt_kernel<<<dim3(64, 16), 256>>>(W);
    vq_main<<<128, 256, SMEM_BYTES>>>(x, W, out);
    finalize_kernel<<<1, 256>>>(out);
}

// round 11
// speedup vs baseline: 3.1191x; 1.7964x over previous
#include <cuda_runtime.h>
#include <cuda_bf16.h>
#include <math.h>
#include <stdint.h>

#define K_CODES 2048
#define DDIM    512
#define N_ROWS  16384
#define QN      8388608
#define OUT_LOSS 0
#define OUT_Q    1
#define OUT_PERP (1+QN)
#define OUT_IDX  (2+QN)

#define BM 128
#define NPANEL 16
#define NCH 8
/* smem byte offsets */
#define SA    0
#define SB0   133120
#define SB1   151552
#define SDIST 169984
#define SCD   203264
#define SCI   207360
#define SWSQ  211456
#define SFSQ  211968
#define SIDX  212480
#define SRED  214016
#define SMEM_BYTES 214048

__device__ __nv_bfloat16 g_xhb[(size_t)N_ROWS * DDIM];
__device__ __nv_bfloat16 g_whb[(size_t)K_CODES * DDIM];
__device__ float g_xt[(size_t)N_ROWS * DDIM];
__device__ float g_wsq[K_CODES];
__device__ float g_fsq[N_ROWS];
__device__ int   g_counts[K_CODES];
__device__ float g_partials[128];

__device__ __forceinline__ uint32_t smem_u32(const void* p) {
    uint32_t a;
    asm("{ .reg .u64 t; cvta.to.shared.u64 t, %1; cvt.u32.u64 %0, t; }" : "=r"(a) : "l"(p));
    return a;
}
__device__ __forceinline__ void ldsm4(uint32_t a, uint32_t& r0, uint32_t& r1, uint32_t& r2, uint32_t& r3) {
    asm volatile("ldmatrix.sync.aligned.m8n8.x4.shared.b16 {%0,%1,%2,%3}, [%4];"
        : "=r"(r0), "=r"(r1), "=r"(r2), "=r"(r3) : "r"(a));
}
__device__ __forceinline__ void mma16816(float* c, uint32_t a0, uint32_t a1, uint32_t a2, uint32_t a3,
                                         uint32_t b0, uint32_t b1) {
    asm volatile("mma.sync.aligned.m16n8k16.row.col.f32.bf16.bf16.f32 "
        "{%0,%1,%2,%3},{%4,%5,%6,%7},{%8,%9},{%0,%1,%2,%3};"
        : "+f"(c[0]), "+f"(c[1]), "+f"(c[2]), "+f"(c[3])
        : "r"(a0), "r"(a1), "r"(a2), "r"(a3), "r"(b0), "r"(b1));
}

__global__ void init_counts() {
    int i = blockIdx.x * blockDim.x + threadIdx.x;
    if (i < K_CODES) g_counts[i] = 0;
}
__global__ void wsq_kernel(const float* __restrict__ W) {
    int warp = (blockIdx.x * blockDim.x + threadIdx.x) >> 5, lane = threadIdx.x & 31;
    if (warp >= K_CODES) return;
    const float* row = W + (size_t)warp * DDIM;
    float s = 0.f;
    for (int d = lane; d < DDIM; d += 32) { float v = row[d]; s += v * v; }
    for (int o = 16; o > 0; o >>= 1) s += __shfl_xor_sync(0xffffffffu, s, o);
    if (lane == 0) g_wsq[warp] = s;
}
__global__ void fsq_kernel(const float* __restrict__ x) {
    int b = blockIdx.x, t = threadIdx.x;
    const float* p = x + (size_t)b * DDIM * 256 + t;
    float s = 0.f;
    for (int d = 0; d < DDIM; d++) { float v = p[(size_t)d * 256]; s += v * v; }
    g_fsq[b * 256 + t] = s;
}
__global__ void conv_w(const float* __restrict__ W) {
    int i = blockIdx.x * blockDim.x + threadIdx.x;
    g_whb[i] = __float2bfloat16_rn(W[i]);
}
__global__ void conv_x(const float* __restrict__ x) {
    __shared__ float sh[64][65];
    int b = blockIdx.z, d0 = blockIdx.y * 64, t0 = blockIdx.x * 64, tid = threadIdx.x;
    #pragma unroll
    for (int i = 0; i < 16; i++) {
        int lin = i * 256 + tid, dd = lin >> 6, tt = lin & 63;
        sh[dd][tt] = x[((size_t)b * DDIM + d0 + dd) * 256 + t0 + tt];
    }
    __syncthreads();
    #pragma unroll
    for (int i = 0; i < 16; i++) {
        int lin = i * 256 + tid, nn = lin >> 6, dd = lin & 63;
        float v = sh[dd][nn];
        size_t o = (size_t)(b * 256 + t0 + nn) * DDIM + d0 + dd;
        g_xt[o] = v;
        g_xhb[o] = __float2bfloat16_rn(v);
    }
}

__global__ __launch_bounds__(256, 1)
void vq_main(const float* __restrict__ x, const float* __restrict__ W,
             float* __restrict__ out) {
    extern __shared__ char sm[];
    const uint32_t smb = smem_u32(sm);
    const int tid = threadIdx.x, wid = tid >> 5, lane = tid & 31;
    const int gr0 = blockIdx.x * BM, m0 = wid * 16;
    float* dist_s = (float*)(sm + SDIST);
    float* cd_s = (float*)(sm + SCD);
    int*   ci_s = (int*)(sm + SCI);
    float* wsq_s = (float*)(sm + SWSQ);
    float* fsq_s = (float*)(sm + SFSQ);
    int*   idx_s = (int*)(sm + SIDX);
    float* red_s = (float*)(sm + SRED);

    if (tid < BM) fsq_s[tid] = g_fsq[gr0 + tid];
    {   /* resident A tile: 128 x 512 bf16, stride 1040B */
        const int4* src = (const int4*)g_xhb;
        for (int i = tid; i < 8192; i += 256) {
            int row = i >> 6, seg = i & 63;
            *(int4*)(sm + SA + row * 1040 + seg * 16) = src[(size_t)(gr0 + row) * 64 + seg];
        }
    }
    const uint32_t aBase = smb + SA +
        (uint32_t)((m0 + ((lane >> 3) & 1) * 8 + (lane & 7)) * 1040 + ((lane >> 4) & 1) * 16);
    const uint32_t bOff =
        (uint32_t)(((((lane >> 4) & 1) * 8) + (lane & 7)) * 144 + ((lane >> 3) & 1) * 16);
    const int bc = tid >> 1, bh = tid & 1;
    const int4* wsrc = (const int4*)g_whb;

    float td[8]; int ti[8];
    #pragma unroll
    for (int s = 0; s < 8; s++) { td[s] = INFINITY; ti[s] = 0; }
    __syncthreads();

    for (int p = 0; p < NPANEL; p++) {
        const int c0 = p * 128;
        if (tid < 128) wsq_s[tid] = g_wsq[c0 + tid];
        #pragma unroll
        for (int j = 0; j < 4; j++)
            *(int4*)(sm + SB0 + bc * 144 + bh * 64 + j * 16) = wsrc[(size_t)(c0 + bc) * 64 + bh * 4 + j];
        __syncthreads();

        float acc[64];
        #pragma unroll
        for (int i = 0; i < 64; i++) acc[i] = 0.f;

        for (int kc = 0; kc < NCH; kc++) {
            int4 pf[4];
            if (kc < NCH - 1)
                #pragma unroll
                for (int j = 0; j < 4; j++)
                    pf[j] = wsrc[(size_t)(c0 + bc) * 64 + (kc + 1) * 8 + bh * 4 + j];
            const uint32_t bufB = smb + ((kc & 1) ? SB1 : SB0);
            #pragma unroll
            for (int k16 = 0; k16 < 4; k16++) {
                uint32_t a0, a1, a2, a3;
                ldsm4(aBase + kc * 128 + k16 * 32, a0, a1, a2, a3);
                #pragma unroll
                for (int n16 = 0; n16 < 8; n16++) {
                    uint32_t b0, b1, b2, b3;
                    ldsm4(bufB + n16 * (16 * 144) + bOff + k16 * 32, b0, b1, b2, b3);
                    mma16816(acc + (n16 * 2 + 0) * 4, a0, a1, a2, a3, b0, b1);
                    mma16816(acc + (n16 * 2 + 1) * 4, a0, a1, a2, a3, b2, b3);
                }
            }
            __syncthreads();
            if (kc < NCH - 1) {
                char* dst = sm + (((kc + 1) & 1) ? SB1 : SB0);
                #pragma unroll
                for (int j = 0; j < 4; j++)
                    *(int4*)(dst + bc * 144 + bh * 64 + j * 16) = pf[j];
                __syncthreads();
            }
        }
        /* two half-panels: write approx dist, owners scan top-8 */
        #pragma unroll
        for (int half = 0; half < 2; half++) {
            const int r0 = m0 + (lane >> 2), cb = (lane & 3) * 2;
            #pragma unroll
            for (int g = 0; g < 8; g++) {
                const int gg = half * 8 + g;
                const int c = g * 8 + cb;
                dist_s[r0 * 65 + c]       = fmaf(-2.f, acc[gg * 4 + 0], wsq_s[half * 64 + c]);
                dist_s[r0 * 65 + c + 1]   = fmaf(-2.f, acc[gg * 4 + 1], wsq_s[half * 64 + c + 1]);
                dist_s[(r0 + 8) * 65 + c]     = fmaf(-2.f, acc[gg * 4 + 2], wsq_s[half * 64 + c]);
                dist_s[(r0 + 8) * 65 + c + 1] = fmaf(-2.f, acc[gg * 4 + 3], wsq_s[half * 64 + c + 1]);
            }
            __syncthreads();
            if (tid < BM) {
                const int cb0 = c0 + half * 64;
                #pragma unroll 8
                for (int c = 0; c < 64; c++) {
                    float dv = dist_s[tid * 65 + c];
                    if (dv < td[7]) {
                        td[7] = dv; ti[7] = cb0 + c;
                        #pragma unroll
                        for (int s = 7; s > 0; s--)
                            if (td[s] < td[s - 1]) {
                                float t1 = td[s]; td[s] = td[s - 1]; td[s - 1] = t1;
                                int t2 = ti[s]; ti[s] = ti[s - 1]; ti[s - 1] = t2;
                            }
                    }
                }
            }
            __syncthreads();
        }
    }
    if (tid < BM)
        #pragma unroll
        for (int s = 0; s < 8; s++) { cd_s[tid * 8 + s] = td[s]; ci_s[tid * 8 + s] = ti[s]; }
    __syncthreads();

    /* exact rescore: same FFMA chain/order as R1 -> bitwise identical dists */
    #pragma unroll 1
    for (int q = 0; q < 4; q++) {
        const int pair = q * 256 + tid, r = pair >> 3;
        const int ci = ci_s[pair];
        const float4* wp = (const float4*)(W + (size_t)ci * DDIM);
        const float4* xp = (const float4*)(g_xt + (size_t)(gr0 + r) * DDIM);
        float s = 0.f;
        #pragma unroll 8
        for (int d4 = 0; d4 < 128; d4++) {
            float4 a = xp[d4], b = wp[d4];
            s = fmaf(a.x, b.x, s); s = fmaf(a.y, b.y, s);
            s = fmaf(a.z, b.z, s); s = fmaf(a.w, b.w, s);
        }
        cd_s[pair] = __fadd_rn(__fadd_rn(fsq_s[r], g_wsq[ci]), -__fmul_rn(2.0f, s));
    }
    __syncthreads();

    if (tid < BM) {
        float b0 = INFINITY, b1 = INFINITY, b2 = INFINITY;
        int i0 = 0x7fffffff, i1 = 0x7fffffff, i2 = 0x7fffffff;
        #pragma unroll
        for (int s = 0; s < 8; s++) {
            float d = cd_s[tid * 8 + s]; int c = ci_s[tid * 8 + s];
            if (d < b0 || (d == b0 && c < i0)) {
                b2 = b1; i2 = i1; b1 = b0; i1 = i0; b0 = d; i0 = c;
            } else if (d < b1 || (d == b1 && c < i1)) {
                b2 = b1; i2 = i1; b1 = d; i1 = c;
            } else if (d < b2 || (d == b2 && c < i2)) {
                b2 = d; i2 = c;
            }
        }
        idx_s[tid * 3 + 0] = i0; idx_s[tid * 3 + 1] = i1; idx_s[tid * 3 + 2] = i2;
        atomicAdd(&g_counts[i0], 1);
        atomicAdd(&g_counts[i1], 1);
        atomicAdd(&g_counts[i2], 1);
        out[OUT_IDX + gr0 + tid] = (float)i2;
    }
    __syncthreads();

    /* quantized output + MSE */
    const int bq = gr0 >> 8, t0 = gr0 & 255;
    float* q_s = (float*)(sm + SA);
    float mse = 0.f;
    const int r = tid & 127, dh = tid >> 7;
    const int j0 = idx_s[r * 3 + 0], j1 = idx_s[r * 3 + 1], j2 = idx_s[r * 3 + 2];
    for (int dc = 0; dc < 16; dc++) {
        const int d0 = dc * 32 + dh * 16;
        #pragma unroll
        for (int q4 = 0; q4 < 4; q4++) {
            float4 a = *(const float4*)(W + (size_t)j0 * DDIM + d0 + q4 * 4);
            float4 bb = *(const float4*)(W + (size_t)j1 * DDIM + d0 + q4 * 4);
            float4 cc = *(const float4*)(W + (size_t)j2 * DDIM + d0 + q4 * 4);
            int dl = dh * 16 + q4 * 4;
            q_s[(dl + 0) * 128 + r] = (a.x + bb.x + cc.x) * (1.0f / 3.0f);
            q_s[(dl + 1) * 128 + r] = (a.y + bb.y + cc.y) * (1.0f / 3.0f);
            q_s[(dl + 2) * 128 + r] = (a.z + bb.z + cc.z) * (1.0f / 3.0f);
            q_s[(dl + 3) * 128 + r] = (a.w + bb.w + cc.w) * (1.0f / 3.0f);
        }
        __syncthreads();
        #pragma unroll
        for (int i = 0; i < 16; i++) {
            int lin = i * 256 + tid, dl = lin >> 7, rr = lin & 127;
            int d = dc * 32 + dl;
            size_t go = (size_t)(bq * DDIM + d) * 256 + t0 + rr;
            float qv = q_s[dl * 128 + rr];
            out[OUT_Q + go] = qv;
            float df = qv - x[go];
            mse += df * df;
        }
        __syncthreads();
    }
    for (int o = 16; o > 0; o >>= 1) mse += __shfl_xor_sync(0xffffffffu, mse, o);
    if (lane == 0) red_s[wid] = mse;
    __syncthreads();
    if (tid == 0) {
        float s = 0.f;
        #pragma unroll
        for (int i = 0; i < 8; i++) s += red_s[i];
        g_partials[blockIdx.x] = s;
    }
}

__global__ void finalize_kernel(float* __restrict__ out) {
    __shared__ float red[256];
    int tid = threadIdx.x;
    red[tid] = (tid < 128) ? g_partials[tid] : 0.f;
    __syncthreads();
    for (int s = 128; s > 0; s >>= 1) {
        if (tid < s) red[tid] += red[tid + s];
        __syncthreads();
    }
    if (tid == 0) out[OUT_LOSS] = 1.25f * (red[0] / (float)QN);
    __syncthreads();
    float e = 0.f;
    for (int k = tid; k < K_CODES; k += 256) {
        float pr = (float)g_counts[k] * (1.0f / (float)N_ROWS);
        e += pr * logf(pr + 1e-10f);
    }
    red[tid] = e;
    __syncthreads();
    for (int s = 128; s > 0; s >>= 1) {
        if (tid < s) red[tid] += red[tid + s];
        __syncthreads();
    }
    if (tid == 0) out[OUT_PERP] = expf(-red[0]);
}

extern "C" void kernel_launch(void* const* d_in, const int* in_sizes, int n_in,
                              void* d_out, int out_size) {
    const float* x = (const float*)d_in[0];
    const float* W = (const float*)d_in[1];
    float* out = (float*)d_out;
    (void)in_sizes; (void)n_in; (void)out_size;
    cudaFuncSetAttribute(vq_main, cudaFuncAttributeMaxDynamicSharedMemorySize, SMEM_BYTES);
    init_counts<<<8, 256>>>();
    wsq_kernel<<<256, 256>>>(W);
    fsq_kernel<<<64, 256>>>(x);
    conv_w<<<4096, 256>>>(W);
    conv_x<<<dim3(4, 8, 64), 256>>>(x);
    vq_main<<<128, 256, SMEM_BYTES>>>(x, W, out);
    finalize_kernel<<<1, 256>>>(out);
}

// round 13
// speedup vs baseline: 3.4778x; 1.1150x over previous
#include <cuda_runtime.h>
#include <cuda_bf16.h>
#include <math.h>
#include <stdint.h>

#define K_CODES 2048
#define DDIM    512
#define N_ROWS  16384
#define QN      8388608
#define OUT_LOSS 0
#define OUT_Q    1
#define OUT_PERP (1+QN)
#define OUT_IDX  (2+QN)

#define BM 128
#define NPANEL 16
#define NCH 8
/* smem byte offsets */
#define SA    0
#define SB0   133120
#define SB1   151552
#define SCD   169984
#define SCI   178176
#define SWSQ  186368
#define SFSQ  186880
#define SIDX  187392
#define SRED  188928
#define SMEM_BYTES 188960

__device__ __nv_bfloat16 g_xhb[(size_t)N_ROWS * DDIM];
__device__ __nv_bfloat16 g_whb[(size_t)K_CODES * DDIM];
__device__ float g_xt[(size_t)N_ROWS * DDIM];
__device__ float g_wsq[K_CODES];
__device__ float g_fsq[N_ROWS];
__device__ int   g_counts[K_CODES];
__device__ float g_partials[128];

__device__ __forceinline__ uint32_t smem_u32(const void* p) {
    uint32_t a;
    asm("{ .reg .u64 t; cvta.to.shared.u64 t, %1; cvt.u32.u64 %0, t; }" : "=r"(a) : "l"(p));
    return a;
}
__device__ __forceinline__ void ldsm4(uint32_t a, uint32_t& r0, uint32_t& r1, uint32_t& r2, uint32_t& r3) {
    asm volatile("ldmatrix.sync.aligned.m8n8.x4.shared.b16 {%0,%1,%2,%3}, [%4];"
        : "=r"(r0), "=r"(r1), "=r"(r2), "=r"(r3) : "r"(a));
}
__device__ __forceinline__ void mma16816(float* c, uint32_t a0, uint32_t a1, uint32_t a2, uint32_t a3,
                                         uint32_t b0, uint32_t b1) {
    asm volatile("mma.sync.aligned.m16n8k16.row.col.f32.bf16.bf16.f32 "
        "{%0,%1,%2,%3},{%4,%5,%6,%7},{%8,%9},{%0,%1,%2,%3};"
        : "+f"(c[0]), "+f"(c[1]), "+f"(c[2]), "+f"(c[3])
        : "r"(a0), "r"(a1), "r"(a2), "r"(a3), "r"(b0), "r"(b1));
}
__device__ __forceinline__ void ins4(float* td, int* ti, float v, int c) {
    if (v < td[3]) {
        td[3] = v; ti[3] = c;
        if (td[3] < td[2]) { float a = td[3]; td[3] = td[2]; td[2] = a; int b = ti[3]; ti[3] = ti[2]; ti[2] = b; }
        if (td[2] < td[1]) { float a = td[2]; td[2] = td[1]; td[1] = a; int b = ti[2]; ti[2] = ti[1]; ti[1] = b; }
        if (td[1] < td[0]) { float a = td[1]; td[1] = td[0]; td[0] = a; int b = ti[1]; ti[1] = ti[0]; ti[0] = b; }
    }
}

__global__ void init_counts() {
    int i = blockIdx.x * blockDim.x + threadIdx.x;
    if (i < K_CODES) g_counts[i] = 0;
}
/* conv W -> bf16 + wsq (same per-lane FP order as the validated wsq_kernel) */
__global__ void conv_w(const float* __restrict__ W) {
    int warp = (blockIdx.x * blockDim.x + threadIdx.x) >> 5, lane = threadIdx.x & 31;
    if (warp >= K_CODES) return;
    const float* row = W + (size_t)warp * DDIM;
    float s = 0.f;
    for (int d = lane; d < DDIM; d += 32) {
        float v = row[d];
        s += v * v;
        g_whb[(size_t)warp * DDIM + d] = __float2bfloat16_rn(v);
    }
    for (int o = 16; o > 0; o >>= 1) s += __shfl_xor_sync(0xffffffffu, s, o);
    if (lane == 0) g_wsq[warp] = s;
}
__global__ void fsq_kernel(const float* __restrict__ x) {
    int b = blockIdx.x, t = threadIdx.x;
    const float* p = x + (size_t)b * DDIM * 256 + t;
    float s = 0.f;
    for (int d = 0; d < DDIM; d++) { float v = p[(size_t)d * 256]; s += v * v; }
    g_fsq[b * 256 + t] = s;
}
__global__ void conv_x(const float* __restrict__ x) {
    __shared__ float sh[64][65];
    int b = blockIdx.z, d0 = blockIdx.y * 64, t0 = blockIdx.x * 64, tid = threadIdx.x;
    #pragma unroll
    for (int i = 0; i < 16; i++) {
        int lin = i * 256 + tid, dd = lin >> 6, tt = lin & 63;
        sh[dd][tt] = x[((size_t)b * DDIM + d0 + dd) * 256 + t0 + tt];
    }
    __syncthreads();
    #pragma unroll
    for (int i = 0; i < 16; i++) {
        int lin = i * 256 + tid, nn = lin >> 6, dd = lin & 63;
        float v = sh[dd][nn];
        size_t o = (size_t)(b * 256 + t0 + nn) * DDIM + d0 + dd;
        g_xt[o] = v;
        g_xhb[o] = __float2bfloat16_rn(v);
    }
}

__global__ __launch_bounds__(256, 1)
void vq_main(const float* __restrict__ x, const float* __restrict__ W,
             float* __restrict__ out) {
    extern __shared__ char sm[];
    const uint32_t smb = smem_u32(sm);
    const int tid = threadIdx.x, wid = tid >> 5, lane = tid & 31;
    const int gr0 = blockIdx.x * BM, m0 = wid * 16;
    float* cd_s = (float*)(sm + SCD);
    int*   ci_s = (int*)(sm + SCI);
    float* wsq_s = (float*)(sm + SWSQ);
    float* fsq_s = (float*)(sm + SFSQ);
    int*   idx_s = (int*)(sm + SIDX);
    float* red_s = (float*)(sm + SRED);

    if (tid < BM) fsq_s[tid] = g_fsq[gr0 + tid];
    {   /* resident A tile: 128 x 512 bf16, stride 1040B */
        const int4* src = (const int4*)g_xhb;
        for (int i = tid; i < 8192; i += 256) {
            int row = i >> 6, seg = i & 63;
            *(int4*)(sm + SA + row * 1040 + seg * 16) = src[(size_t)(gr0 + row) * 64 + seg];
        }
    }
    const uint32_t aBase = smb + SA +
        (uint32_t)((m0 + ((lane >> 3) & 1) * 8 + (lane & 7)) * 1040 + ((lane >> 4) & 1) * 16);
    const uint32_t bOff =
        (uint32_t)(((((lane >> 4) & 1) * 8) + (lane & 7)) * 144 + ((lane >> 3) & 1) * 16);
    const int bc = tid >> 1, bh = tid & 1;
    const int lq = lane & 3;
    const int4* wsrc = (const int4*)g_whb;

    float td0[4], td1[4]; int ti0[4], ti1[4];
    #pragma unroll
    for (int s = 0; s < 4; s++) {
        td0[s] = INFINITY; td1[s] = INFINITY; ti0[s] = 0; ti1[s] = 0;
    }

    for (int p = 0; p < NPANEL; p++) {
        const int c0 = p * 128;
        __syncthreads();                 /* wsq_s WAR vs prior screening */
        if (tid < 128) wsq_s[tid] = g_wsq[c0 + tid];
        #pragma unroll
        for (int j = 0; j < 4; j++)
            *(int4*)(sm + SB0 + bc * 144 + bh * 64 + j * 16) = wsrc[(size_t)(c0 + bc) * 64 + bh * 4 + j];
        __syncthreads();

        float acc[64];
        #pragma unroll
        for (int i = 0; i < 64; i++) acc[i] = 0.f;

        for (int kc = 0; kc < NCH; kc++) {
            int4 pf[4];
            if (kc < NCH - 1)
                #pragma unroll
                for (int j = 0; j < 4; j++)
                    pf[j] = wsrc[(size_t)(c0 + bc) * 64 + (kc + 1) * 8 + bh * 4 + j];
            const uint32_t bufB = smb + ((kc & 1) ? SB1 : SB0);
            #pragma unroll
            for (int k16 = 0; k16 < 4; k16++) {
                uint32_t a0, a1, a2, a3;
                ldsm4(aBase + kc * 128 + k16 * 32, a0, a1, a2, a3);
                #pragma unroll
                for (int n16 = 0; n16 < 8; n16++) {
                    uint32_t b0, b1, b2, b3;
                    ldsm4(bufB + n16 * (16 * 144) + bOff + k16 * 32, b0, b1, b2, b3);
                    mma16816(acc + (n16 * 2 + 0) * 4, a0, a1, a2, a3, b0, b1);
                    mma16816(acc + (n16 * 2 + 1) * 4, a0, a1, a2, a3, b2, b3);
                }
            }
            __syncthreads();
            if (kc < NCH - 1) {
                char* dst = sm + (((kc + 1) & 1) ? SB1 : SB0);
                #pragma unroll
                for (int j = 0; j < 4; j++)
                    *(int4*)(dst + bc * 144 + bh * 64 + j * 16) = pf[j];
                __syncthreads();
            }
        }
        /* in-register screening: per-thread top-4 per row over own columns */
        #pragma unroll
        for (int gg = 0; gg < 16; gg++) {
            const int c = (gg >> 3) * 64 + (gg & 7) * 8 + lq * 2;
            const float w0 = wsq_s[c], w1 = wsq_s[c + 1];
            const int code = c0 + c;
            ins4(td0, ti0, fmaf(-2.f, acc[gg * 4 + 0], w0), code);
            ins4(td0, ti0, fmaf(-2.f, acc[gg * 4 + 1], w1), code + 1);
            ins4(td1, ti1, fmaf(-2.f, acc[gg * 4 + 2], w0), code);
            ins4(td1, ti1, fmaf(-2.f, acc[gg * 4 + 3], w1), code + 1);
        }
    }
    {   /* dump 16 candidates per row (4 lanes x 4) */
        const int r0 = m0 + (lane >> 2);
        #pragma unroll
        for (int s = 0; s < 4; s++) {
            cd_s[r0 * 16 + lq * 4 + s] = td0[s]; ci_s[r0 * 16 + lq * 4 + s] = ti0[s];
            cd_s[(r0 + 8) * 16 + lq * 4 + s] = td1[s]; ci_s[(r0 + 8) * 16 + lq * 4 + s] = ti1[s];
        }
    }
    __syncthreads();

    /* exact rescore: same FFMA chain/order as R1 -> bitwise identical dists */
    #pragma unroll 1
    for (int q = 0; q < 8; q++) {
        const int pair = q * 256 + tid, r = pair >> 4;
        const int ci = ci_s[pair];
        const float4* wp = (const float4*)(W + (size_t)ci * DDIM);
        const float4* xp = (const float4*)(g_xt + (size_t)(gr0 + r) * DDIM);
        float s = 0.f;
        #pragma unroll 8
        for (int d4 = 0; d4 < 128; d4++) {
            float4 a = xp[d4], b = wp[d4];
            s = fmaf(a.x, b.x, s); s = fmaf(a.y, b.y, s);
            s = fmaf(a.z, b.z, s); s = fmaf(a.w, b.w, s);
        }
        cd_s[pair] = __fadd_rn(__fadd_rn(fsq_s[r], g_wsq[ci]), -__fmul_rn(2.0f, s));
    }
    __syncthreads();

    if (tid < BM) {
        float b0 = INFINITY, b1 = INFINITY, b2 = INFINITY;
        int i0 = 0x7fffffff, i1 = 0x7fffffff, i2 = 0x7fffffff;
        #pragma unroll
        for (int s = 0; s < 16; s++) {
            float d = cd_s[tid * 16 + s]; int c = ci_s[tid * 16 + s];
            if (d < b0 || (d == b0 && c < i0)) {
                b2 = b1; i2 = i1; b1 = b0; i1 = i0; b0 = d; i0 = c;
            } else if (d < b1 || (d == b1 && c < i1)) {
                b2 = b1; i2 = i1; b1 = d; i1 = c;
            } else if (d < b2 || (d == b2 && c < i2)) {
                b2 = d; i2 = c;
            }
        }
        idx_s[tid * 3 + 0] = i0; idx_s[tid * 3 + 1] = i1; idx_s[tid * 3 + 2] = i2;
        atomicAdd(&g_counts[i0], 1);
        atomicAdd(&g_counts[i1], 1);
        atomicAdd(&g_counts[i2], 1);
        out[OUT_IDX + gr0 + tid] = (float)i2;
    }
    __syncthreads();

    /* quantized output + MSE */
    const int bq = gr0 >> 8, t0 = gr0 & 255;
    float* q_s = (float*)(sm + SA);
    float mse = 0.f;
    const int r = tid & 127, dh = tid >> 7;
    const int j0 = idx_s[r * 3 + 0], j1 = idx_s[r * 3 + 1], j2 = idx_s[r * 3 + 2];
    for (int dc = 0; dc < 16; dc++) {
        const int d0 = dc * 32 + dh * 16;
        #pragma unroll
        for (int q4 = 0; q4 < 4; q4++) {
            float4 a = *(const float4*)(W + (size_t)j0 * DDIM + d0 + q4 * 4);
            float4 bb = *(const float4*)(W + (size_t)j1 * DDIM + d0 + q4 * 4);
            float4 cc = *(const float4*)(W + (size_t)j2 * DDIM + d0 + q4 * 4);
            int dl = dh * 16 + q4 * 4;
            q_s[(dl + 0) * 128 + r] = (a.x + bb.x + cc.x) * (1.0f / 3.0f);
            q_s[(dl + 1) * 128 + r] = (a.y + bb.y + cc.y) * (1.0f / 3.0f);
            q_s[(dl + 2) * 128 + r] = (a.z + bb.z + cc.z) * (1.0f / 3.0f);
            q_s[(dl + 3) * 128 + r] = (a.w + bb.w + cc.w) * (1.0f / 3.0f);
        }
        __syncthreads();
        #pragma unroll
        for (int i = 0; i < 16; i++) {
            int lin = i * 256 + tid, dl = lin >> 7, rr = lin & 127;
            int d = dc * 32 + dl;
            size_t go = (size_t)(bq * DDIM + d) * 256 + t0 + rr;
            float qv = q_s[dl * 128 + rr];
            out[OUT_Q + go] = qv;
            float df = qv - x[go];
            mse += df * df;
        }
        __syncthreads();
    }
    for (int o = 16; o > 0; o >>= 1) mse += __shfl_xor_sync(0xffffffffu, mse, o);
    if (lane == 0) red_s[wid] = mse;
    __syncthreads();
    if (tid == 0) {
        float s = 0.f;
        #pragma unroll
        for (int i = 0; i < 8; i++) s += red_s[i];
        g_partials[blockIdx.x] = s;
    }
}

__global__ void finalize_kernel(float* __restrict__ out) {
    __shared__ float red[256];
    int tid = threadIdx.x;
    red[tid] = (tid < 128) ? g_partials[tid] : 0.f;
    __syncthreads();
    for (int s = 128; s > 0; s >>= 1) {
        if (tid < s) red[tid] += red[tid + s];
        __syncthreads();
    }
    if (tid == 0) out[OUT_LOSS] = 1.25f * (red[0] / (float)QN);
    __syncthreads();
    float e = 0.f;
    for (int k = tid; k < K_CODES; k += 256) {
        float pr = (float)g_counts[k] * (1.0f / (float)N_ROWS);
        e += pr * logf(pr + 1e-10f);
    }
    red[tid] = e;
    __syncthreads();
    for (int s = 128; s > 0; s >>= 1) {
        if (tid < s) red[tid] += red[tid + s];
        __syncthreads();
    }
    if (tid == 0) out[OUT_PERP] = expf(-red[0]);
}

extern "C" void kernel_launch(void* const* d_in, const int* in_sizes, int n_in,
                              void* d_out, int out_size) {
    const float* x = (const float*)d_in[0];
    const float* W = (const float*)d_in[1];
    float* out = (float*)d_out;
    (void)in_sizes; (void)n_in; (void)out_size;
    cudaFuncSetAttribute(vq_main, cudaFuncAttributeMaxDynamicSharedMemorySize, SMEM_BYTES);
    init_counts<<<8, 256>>>();
    conv_w<<<256, 256>>>(W);
    fsq_kernel<<<64, 256>>>(x);
    conv_x<<<dim3(4, 8, 64), 256>>>(x);
    vq_main<<<128, 256, SMEM_BYTES>>>(x, W, out);
    finalize_kernel<<<1, 256>>>(out);
}